// round 1
// baseline (speedup 1.0000x reference)
#include <cuda_runtime.h>
#include <cuda_bf16.h>
#include <cstdint>

// Problem constants (fixed by the reference).
#define N_ENT   50000
#define N_REL   16
#define N_BASES 8
#define H_DIM   128
#define N_EDGES 800000

// ---------------------------------------------------------------------------
// Device scratch (allocation-free rule: __device__ globals).
// g_W  : [17][128][128]  combined relation matrices; slot 16 = loop_w
// g_HR : [16][N_ENT][128] per-relation transformed embeddings
// g_H1 : [N_ENT][128]     layer-1 pre-ReLU output
// ---------------------------------------------------------------------------
__device__ float g_W[17 * H_DIM * H_DIM];
__device__ float g_HR[(size_t)N_REL * N_ENT * H_DIM];
__device__ float g_H1[(size_t)N_ENT * H_DIM];

// ---------------------------------------------------------------------------
// 1) Combine bases: W[r,i,o] = sum_b w_comp[r,b] * basis[b,i,o];  W[16] = loop_w
// ---------------------------------------------------------------------------
__global__ void combine_bases_kernel(const float* __restrict__ basis,
                                     const float* __restrict__ w_comp,
                                     const float* __restrict__ loop_w,
                                     float* __restrict__ W)
{
    int idx = blockIdx.x * blockDim.x + threadIdx.x;
    const int total = 17 * H_DIM * H_DIM;
    if (idx >= total) return;
    int r  = idx >> 14;          // / 16384
    int io = idx & 16383;
    if (r < N_REL) {
        float s = 0.f;
#pragma unroll
        for (int b = 0; b < N_BASES; b++)
            s += w_comp[r * N_BASES + b] * basis[b * (H_DIM * H_DIM) + io];
        W[idx] = s;
    } else {
        W[idx] = loop_w[io];
    }
}

// ---------------------------------------------------------------------------
// 2) SGEMM: for each r in [0,17): C_r = relu?(A) @ W[r]
//    A: [M,128] row-major.  W[r]: [128,128] row-major (i -> o).
//    r < 16  : write to HR + r*M*128
//    r == 16 : write to OUT (+bias)  -- initializes the output buffer
//    CTA tile 128x128, 256 threads, each thread 8x8 microtile, BK=16.
// ---------------------------------------------------------------------------
#define BM 128
#define BN 128
#define BK 16

__global__ __launch_bounds__(256, 2)
void gemm_kernel(const float* __restrict__ A,
                 const float* __restrict__ Wfull,
                 const float* __restrict__ bias,
                 float* __restrict__ HR,
                 float* __restrict__ OUT,
                 int M, int reluA)
{
    __shared__ float As[BK][BM + 4];   // transposed A tile (k, m)
    __shared__ float Bs[BK][BN];

    const int r  = blockIdx.x;         // 0..16
    const int m0 = blockIdx.y * BM;
    const float* B = Wfull + (size_t)r * H_DIM * H_DIM;

    const int tid = threadIdx.x;       // 0..255
    const int ty  = tid >> 4;          // 0..15 (row group)
    const int tx  = tid & 15;          // 0..15 (col group)

    float acc[8][8];
#pragma unroll
    for (int i = 0; i < 8; i++)
#pragma unroll
        for (int j = 0; j < 8; j++) acc[i][j] = 0.f;

    for (int kk = 0; kk < H_DIM; kk += BK) {
        // ---- load A tile: 128 rows x 16 cols = 512 float4, 2 per thread ----
#pragma unroll
        for (int t = 0; t < 2; t++) {
            int f   = tid * 2 + t;          // 0..511
            int row = f >> 2;               // 0..127
            int c4  = (f & 3) * 4;          // 0,4,8,12
            int grow = m0 + row;
            float4 v = make_float4(0.f, 0.f, 0.f, 0.f);
            if (grow < M)
                v = *(const float4*)(A + (size_t)grow * H_DIM + kk + c4);
            if (reluA) {
                v.x = fmaxf(v.x, 0.f); v.y = fmaxf(v.y, 0.f);
                v.z = fmaxf(v.z, 0.f); v.w = fmaxf(v.w, 0.f);
            }
            As[c4 + 0][row] = v.x;
            As[c4 + 1][row] = v.y;
            As[c4 + 2][row] = v.z;
            As[c4 + 3][row] = v.w;
        }
        // ---- load B tile: 16 rows x 128 cols = 512 float4, 2 per thread ----
#pragma unroll
        for (int t = 0; t < 2; t++) {
            int f   = tid * 2 + t;          // 0..511
            int row = f >> 5;               // 0..15
            int c4  = (f & 31) * 4;         // 0..124
            float4 v = *(const float4*)(B + (size_t)(kk + row) * H_DIM + c4);
            *(float4*)&Bs[row][c4] = v;
        }
        __syncthreads();

#pragma unroll
        for (int k = 0; k < BK; k++) {
            float a[8], b[8];
#pragma unroll
            for (int i = 0; i < 8; i++) a[i] = As[k][ty * 8 + i];
#pragma unroll
            for (int j = 0; j < 8; j++) b[j] = Bs[k][tx * 8 + j];
#pragma unroll
            for (int i = 0; i < 8; i++)
#pragma unroll
                for (int j = 0; j < 8; j++)
                    acc[i][j] = fmaf(a[i], b[j], acc[i][j]);
        }
        __syncthreads();
    }

    // ---- writeback ----
    const int col = tx * 8;
    if (r < N_REL) {
        float* base = HR + (size_t)r * M * H_DIM;
#pragma unroll
        for (int i = 0; i < 8; i++) {
            int row = m0 + ty * 8 + i;
            if (row >= M) break;
            float* c = base + (size_t)row * H_DIM + col;
            *(float4*)c       = make_float4(acc[i][0], acc[i][1], acc[i][2], acc[i][3]);
            *((float4*)c + 1) = make_float4(acc[i][4], acc[i][5], acc[i][6], acc[i][7]);
        }
    } else {
        float bv[8];
#pragma unroll
        for (int j = 0; j < 8; j++) bv[j] = bias[col + j];
#pragma unroll
        for (int i = 0; i < 8; i++) {
            int row = m0 + ty * 8 + i;
            if (row >= M) break;
            float* c = OUT + (size_t)row * H_DIM + col;
            *(float4*)c       = make_float4(acc[i][0] + bv[0], acc[i][1] + bv[1],
                                            acc[i][2] + bv[2], acc[i][3] + bv[3]);
            *((float4*)c + 1) = make_float4(acc[i][4] + bv[4], acc[i][5] + bv[5],
                                            acc[i][6] + bv[6], acc[i][7] + bv[7]);
        }
    }
}

// ---------------------------------------------------------------------------
// 3) Edge scatter: out[dst] += HR[rel][src]. One warp per edge,
//    each lane: float4 gather + 4 scalar atomicAdds.
// ---------------------------------------------------------------------------
__global__ void scatter_kernel(const float* __restrict__ HR,
                               const int* __restrict__ src,
                               const int* __restrict__ dst,
                               const int* __restrict__ rel,
                               float* __restrict__ out,
                               int E)
{
    int gtid = blockIdx.x * blockDim.x + threadIdx.x;
    int e    = gtid >> 5;
    int lane = gtid & 31;
    if (e >= E) return;
    int s = src[e];
    int d = dst[e];
    int r = rel[e];
    const float4 v = *(const float4*)(HR + ((size_t)r * N_ENT + s) * H_DIM + lane * 4);
    float* o = out + (size_t)d * H_DIM + lane * 4;
    atomicAdd(o + 0, v.x);
    atomicAdd(o + 1, v.y);
    atomicAdd(o + 2, v.z);
    atomicAdd(o + 3, v.w);
}

// ---------------------------------------------------------------------------
// 4) Final ReLU (layer-1 ReLU is fused into layer-2's GEMM A-load).
// ---------------------------------------------------------------------------
__global__ void relu_kernel(float* __restrict__ x, size_t n4)
{
    size_t i = (size_t)blockIdx.x * blockDim.x + threadIdx.x;
    if (i >= n4) return;
    float4 v = ((float4*)x)[i];
    v.x = fmaxf(v.x, 0.f); v.y = fmaxf(v.y, 0.f);
    v.z = fmaxf(v.z, 0.f); v.w = fmaxf(v.w, 0.f);
    ((float4*)x)[i] = v;
}

// ---------------------------------------------------------------------------
// Launch: inputs per metadata order:
// 0 entity_emb, 1 basis1, 2 w_comp1, 3 loop_w1, 4 bias1,
// 5 basis2, 6 w_comp2, 7 loop_w2, 8 bias2, 9 src, 10 dst, 11 rel_type
// ---------------------------------------------------------------------------
extern "C" void kernel_launch(void* const* d_in, const int* in_sizes, int n_in,
                              void* d_out, int out_size)
{
    const float* entity_emb = (const float*)d_in[0];
    const float* basis1     = (const float*)d_in[1];
    const float* w_comp1    = (const float*)d_in[2];
    const float* loop_w1    = (const float*)d_in[3];
    const float* bias1      = (const float*)d_in[4];
    const float* basis2     = (const float*)d_in[5];
    const float* w_comp2    = (const float*)d_in[6];
    const float* loop_w2    = (const float*)d_in[7];
    const float* bias2      = (const float*)d_in[8];
    const int*   src        = (const int*)d_in[9];
    const int*   dst        = (const int*)d_in[10];
    const int*   rel        = (const int*)d_in[11];
    float*       out        = (float*)d_out;

    const int E = in_sizes[9];

    float* dW;
    float* dHR;
    float* dH1;
    cudaGetSymbolAddress((void**)&dW,  g_W);
    cudaGetSymbolAddress((void**)&dHR, g_HR);
    cudaGetSymbolAddress((void**)&dH1, g_H1);

    const int cb_total  = 17 * H_DIM * H_DIM;
    const int cb_blocks = (cb_total + 255) / 256;
    dim3 gemm_grid(17, (N_ENT + BM - 1) / BM);
    const int scat_blocks = (E * 32 + 255) / 256;
    const size_t n4 = (size_t)N_ENT * H_DIM / 4;
    const int relu_blocks = (int)((n4 + 255) / 256);

    // ---------------- Layer 1 ----------------
    combine_bases_kernel<<<cb_blocks, 256>>>(basis1, w_comp1, loop_w1, dW);
    gemm_kernel<<<gemm_grid, 256>>>(entity_emb, dW, bias1, dHR, dH1, N_ENT, 0);
    scatter_kernel<<<scat_blocks, 256>>>(dHR, src, dst, rel, dH1, E);
    // (ReLU of dH1 fused into next GEMM's A-load)

    // ---------------- Layer 2 ----------------
    combine_bases_kernel<<<cb_blocks, 256>>>(basis2, w_comp2, loop_w2, dW);
    gemm_kernel<<<gemm_grid, 256>>>(dH1, dW, bias2, dHR, out, N_ENT, 1);
    scatter_kernel<<<scat_blocks, 256>>>(dHR, src, dst, rel, out, E);
    relu_kernel<<<relu_blocks, 256>>>(out, n4);
}

// round 2
// speedup vs baseline: 1.1842x; 1.1842x over previous
#include <cuda_runtime.h>
#include <cuda_bf16.h>
#include <cstdint>

// Problem constants (fixed by the reference).
#define N_ENT   50000
#define N_REL   16
#define N_BASES 8
#define H_DIM   128
#define N_EDGES 800000

// ---------------------------------------------------------------------------
// Device scratch (allocation-free rule: __device__ globals).
// ---------------------------------------------------------------------------
__device__ float g_W[17 * H_DIM * H_DIM];
__device__ float g_HR[(size_t)N_REL * N_ENT * H_DIM];
__device__ float g_H1[(size_t)N_ENT * H_DIM];

// ---------------------------------------------------------------------------
// helpers
// ---------------------------------------------------------------------------
__device__ __forceinline__ uint32_t f2tf32(float f) {
    uint32_t u;
    asm("cvt.rna.tf32.f32 %0, %1;" : "=r"(u) : "f"(f));
    return u;
}

#define MMA_TF32(C, A0, A1, A2, A3, B0, B1)                                   \
    asm volatile(                                                             \
        "mma.sync.aligned.m16n8k8.row.col.f32.tf32.tf32.f32 "                 \
        "{%0,%1,%2,%3}, {%4,%5,%6,%7}, {%8,%9}, {%0,%1,%2,%3};"               \
        : "+f"((C)[0]), "+f"((C)[1]), "+f"((C)[2]), "+f"((C)[3])              \
        : "r"(A0), "r"(A1), "r"(A2), "r"(A3), "r"(B0), "r"(B1))

// ---------------------------------------------------------------------------
// 1) Combine bases: W[r] = sum_b w_comp[r,b]*basis[b];  W[16] = loop_w
// ---------------------------------------------------------------------------
__global__ void combine_bases_kernel(const float* __restrict__ basis,
                                     const float* __restrict__ w_comp,
                                     const float* __restrict__ loop_w,
                                     float* __restrict__ W)
{
    int idx = blockIdx.x * blockDim.x + threadIdx.x;
    const int total = 17 * H_DIM * H_DIM;
    if (idx >= total) return;
    int r  = idx >> 14;
    int io = idx & 16383;
    if (r < N_REL) {
        float s = 0.f;
#pragma unroll
        for (int b = 0; b < N_BASES; b++)
            s += w_comp[r * N_BASES + b] * basis[b * (H_DIM * H_DIM) + io];
        W[idx] = s;
    } else {
        W[idx] = loop_w[io];
    }
}

// ---------------------------------------------------------------------------
// 2) tf32x3 tensor-core GEMM:  C_r = relu?(A) @ W[r]  for r in [0,17)
//    CTA tile 64x128, 128 threads (4 warps, 2x2), warp tile 32x64.
//    Split each input x = hi + lo (tf32); C = hi*hi + lo*hi + hi*lo
//    (error ~ eps^2 ~ 2e-7, fp32-grade).
//    r < 16  -> HR[r];  r == 16 -> OUT (+bias), which initializes OUT.
// ---------------------------------------------------------------------------
#define BM   64
#define BN   128
#define BK   16
#define APAD 20
#define BPAD 132

__global__ __launch_bounds__(128)
void gemm_tf32_kernel(const float* __restrict__ A,
                      const float* __restrict__ Wfull,
                      const float* __restrict__ bias,
                      float* __restrict__ HR,
                      float* __restrict__ OUT,
                      int M, int reluA)
{
    __shared__ uint32_t As_hi[BM][APAD];
    __shared__ uint32_t As_lo[BM][APAD];
    __shared__ uint32_t Bs_hi[BK][BPAD];
    __shared__ uint32_t Bs_lo[BK][BPAD];

    const int r   = blockIdx.x;              // 0..16
    const int m0  = blockIdx.y * BM;
    const float* B = Wfull + (size_t)r * H_DIM * H_DIM;

    const int tid  = threadIdx.x;            // 0..127
    const int wid  = tid >> 5;
    const int lane = tid & 31;
    const int g    = lane >> 2;              // 0..7
    const int t    = lane & 3;               // 0..3
    const int wm   = wid & 1;                // warp row (2 x 32 rows)
    const int wn   = wid >> 1;               // warp col (2 x 64 cols)

    float acc[2][8][4];
#pragma unroll
    for (int mt = 0; mt < 2; mt++)
#pragma unroll
        for (int nt = 0; nt < 8; nt++)
#pragma unroll
            for (int c = 0; c < 4; c++) acc[mt][nt][c] = 0.f;

    for (int kc = 0; kc < H_DIM / BK; kc++) {
        const int kk = kc * BK;

        // ---- A tile: 64x16 floats = 256 float4, 2 per thread ----
#pragma unroll
        for (int tdx = 0; tdx < 2; tdx++) {
            int f    = tid + tdx * 128;      // 0..255
            int row  = f >> 2;               // 0..63
            int c4   = (f & 3) * 4;          // 0,4,8,12
            int grow = m0 + row;
            float4 v = make_float4(0.f, 0.f, 0.f, 0.f);
            if (grow < M)
                v = *(const float4*)(A + (size_t)grow * H_DIM + kk + c4);
            if (reluA) {
                v.x = fmaxf(v.x, 0.f); v.y = fmaxf(v.y, 0.f);
                v.z = fmaxf(v.z, 0.f); v.w = fmaxf(v.w, 0.f);
            }
            float e[4] = {v.x, v.y, v.z, v.w};
#pragma unroll
            for (int j = 0; j < 4; j++) {
                uint32_t hb = f2tf32(e[j]);
                float    hf = __uint_as_float(hb);
                As_hi[row][c4 + j] = hb;
                As_lo[row][c4 + j] = f2tf32(e[j] - hf);
            }
        }
        // ---- B tile: 16x128 floats = 512 float4, 4 per thread ----
#pragma unroll
        for (int tdx = 0; tdx < 4; tdx++) {
            int f   = tid + tdx * 128;       // 0..511
            int row = f >> 5;                // 0..15
            int c4  = (f & 31) * 4;          // 0..124
            float4 v = *(const float4*)(B + (size_t)(kk + row) * H_DIM + c4);
            float e[4] = {v.x, v.y, v.z, v.w};
#pragma unroll
            for (int j = 0; j < 4; j++) {
                uint32_t hb = f2tf32(e[j]);
                float    hf = __uint_as_float(hb);
                Bs_hi[row][c4 + j] = hb;
                Bs_lo[row][c4 + j] = f2tf32(e[j] - hf);
            }
        }
        __syncthreads();

#pragma unroll
        for (int ks = 0; ks < BK / 8; ks++) {
            const int k0 = ks * 8;
            uint32_t ah[2][4], al[2][4], bh[8][2], bl[8][2];
#pragma unroll
            for (int mt = 0; mt < 2; mt++) {
                int mrow = wm * 32 + mt * 16 + g;
                ah[mt][0] = As_hi[mrow    ][k0 + t];
                ah[mt][1] = As_hi[mrow + 8][k0 + t];
                ah[mt][2] = As_hi[mrow    ][k0 + t + 4];
                ah[mt][3] = As_hi[mrow + 8][k0 + t + 4];
                al[mt][0] = As_lo[mrow    ][k0 + t];
                al[mt][1] = As_lo[mrow + 8][k0 + t];
                al[mt][2] = As_lo[mrow    ][k0 + t + 4];
                al[mt][3] = As_lo[mrow + 8][k0 + t + 4];
            }
#pragma unroll
            for (int nt = 0; nt < 8; nt++) {
                int ncol = wn * 64 + nt * 8 + g;
                bh[nt][0] = Bs_hi[k0 + t    ][ncol];
                bh[nt][1] = Bs_hi[k0 + t + 4][ncol];
                bl[nt][0] = Bs_lo[k0 + t    ][ncol];
                bl[nt][1] = Bs_lo[k0 + t + 4][ncol];
            }
#pragma unroll
            for (int mt = 0; mt < 2; mt++)
#pragma unroll
                for (int nt = 0; nt < 8; nt++) {
                    MMA_TF32(acc[mt][nt], ah[mt][0], ah[mt][1], ah[mt][2], ah[mt][3],
                             bh[nt][0], bh[nt][1]);
                    MMA_TF32(acc[mt][nt], al[mt][0], al[mt][1], al[mt][2], al[mt][3],
                             bh[nt][0], bh[nt][1]);
                    MMA_TF32(acc[mt][nt], ah[mt][0], ah[mt][1], ah[mt][2], ah[mt][3],
                             bl[nt][0], bl[nt][1]);
                }
        }
        __syncthreads();
    }

    // ---- epilogue ----
    if (r < N_REL) {
        float* base = HR + (size_t)r * N_ENT * H_DIM;
#pragma unroll
        for (int mt = 0; mt < 2; mt++) {
            int row0 = m0 + wm * 32 + mt * 16 + g;
#pragma unroll
            for (int half = 0; half < 2; half++) {
                int row = row0 + half * 8;
                if (row >= M) continue;
#pragma unroll
                for (int nt = 0; nt < 8; nt++) {
                    int c = wn * 64 + nt * 8 + t * 2;
                    float2 v = half == 0
                        ? make_float2(acc[mt][nt][0], acc[mt][nt][1])
                        : make_float2(acc[mt][nt][2], acc[mt][nt][3]);
                    *(float2*)(base + (size_t)row * H_DIM + c) = v;
                }
            }
        }
    } else {
#pragma unroll
        for (int mt = 0; mt < 2; mt++) {
            int row0 = m0 + wm * 32 + mt * 16 + g;
#pragma unroll
            for (int half = 0; half < 2; half++) {
                int row = row0 + half * 8;
                if (row >= M) continue;
#pragma unroll
                for (int nt = 0; nt < 8; nt++) {
                    int c = wn * 64 + nt * 8 + t * 2;
                    float b0 = bias[c], b1 = bias[c + 1];
                    float2 v = half == 0
                        ? make_float2(acc[mt][nt][0] + b0, acc[mt][nt][1] + b1)
                        : make_float2(acc[mt][nt][2] + b0, acc[mt][nt][3] + b1);
                    *(float2*)(OUT + (size_t)row * H_DIM + c) = v;
                }
            }
        }
    }
}

// ---------------------------------------------------------------------------
// 3) Edge scatter: out[dst] += HR[rel][src]. One warp per edge,
//    each lane: float4 gather + one red.global.add.v4.f32.
// ---------------------------------------------------------------------------
__global__ void scatter_kernel(const float* __restrict__ HR,
                               const int* __restrict__ src,
                               const int* __restrict__ dst,
                               const int* __restrict__ rel,
                               float* __restrict__ out,
                               int E)
{
    int gtid = blockIdx.x * blockDim.x + threadIdx.x;
    int e    = gtid >> 5;
    int lane = gtid & 31;
    if (e >= E) return;
    int s = src[e];
    int d = dst[e];
    int r = rel[e];
    const float4 v = *(const float4*)(HR + ((size_t)r * N_ENT + s) * H_DIM + lane * 4);
    float* o = out + (size_t)d * H_DIM + lane * 4;
    asm volatile("red.global.add.v4.f32 [%0], {%1,%2,%3,%4};"
                 :: "l"(o), "f"(v.x), "f"(v.y), "f"(v.z), "f"(v.w)
                 : "memory");
}

// ---------------------------------------------------------------------------
// 4) Final ReLU (layer-1 ReLU is fused into layer-2's GEMM A-load).
// ---------------------------------------------------------------------------
__global__ void relu_kernel(float* __restrict__ x, size_t n4)
{
    size_t i = (size_t)blockIdx.x * blockDim.x + threadIdx.x;
    if (i >= n4) return;
    float4 v = ((float4*)x)[i];
    v.x = fmaxf(v.x, 0.f); v.y = fmaxf(v.y, 0.f);
    v.z = fmaxf(v.z, 0.f); v.w = fmaxf(v.w, 0.f);
    ((float4*)x)[i] = v;
}

// ---------------------------------------------------------------------------
// Launch
// ---------------------------------------------------------------------------
extern "C" void kernel_launch(void* const* d_in, const int* in_sizes, int n_in,
                              void* d_out, int out_size)
{
    const float* entity_emb = (const float*)d_in[0];
    const float* basis1     = (const float*)d_in[1];
    const float* w_comp1    = (const float*)d_in[2];
    const float* loop_w1    = (const float*)d_in[3];
    const float* bias1      = (const float*)d_in[4];
    const float* basis2     = (const float*)d_in[5];
    const float* w_comp2    = (const float*)d_in[6];
    const float* loop_w2    = (const float*)d_in[7];
    const float* bias2      = (const float*)d_in[8];
    const int*   src        = (const int*)d_in[9];
    const int*   dst        = (const int*)d_in[10];
    const int*   rel        = (const int*)d_in[11];
    float*       out        = (float*)d_out;

    const int E = in_sizes[9];

    float* dW;
    float* dHR;
    float* dH1;
    cudaGetSymbolAddress((void**)&dW,  g_W);
    cudaGetSymbolAddress((void**)&dHR, g_HR);
    cudaGetSymbolAddress((void**)&dH1, g_H1);

    const int cb_total  = 17 * H_DIM * H_DIM;
    const int cb_blocks = (cb_total + 255) / 256;
    dim3 gemm_grid(17, (N_ENT + BM - 1) / BM);
    const int scat_blocks = (E * 32 + 255) / 256;
    const size_t n4 = (size_t)N_ENT * H_DIM / 4;
    const int relu_blocks = (int)((n4 + 255) / 256);

    // ---------------- Layer 1 ----------------
    combine_bases_kernel<<<cb_blocks, 256>>>(basis1, w_comp1, loop_w1, dW);
    gemm_tf32_kernel<<<gemm_grid, 128>>>(entity_emb, dW, bias1, dHR, dH1, N_ENT, 0);
    scatter_kernel<<<scat_blocks, 256>>>(dHR, src, dst, rel, dH1, E);
    // (ReLU of dH1 fused into next GEMM's A-load)

    // ---------------- Layer 2 ----------------
    combine_bases_kernel<<<cb_blocks, 256>>>(basis2, w_comp2, loop_w2, dW);
    gemm_tf32_kernel<<<gemm_grid, 128>>>(dH1, dW, bias2, dHR, out, N_ENT, 1);
    scatter_kernel<<<scat_blocks, 256>>>(dHR, src, dst, rel, out, E);
    relu_kernel<<<relu_blocks, 256>>>(out, n4);
}

// round 4
// speedup vs baseline: 2.2293x; 1.8825x over previous
#include <cuda_runtime.h>
#include <cuda_bf16.h>
#include <cstdint>

// Problem constants (fixed by the reference).
#define N_ENT   50000
#define N_REL   16
#define N_BASES 8
#define H_DIM   128
#define N_EDGES 800000

// ---------------------------------------------------------------------------
// Device scratch (allocation-free rule: __device__ globals).
// ---------------------------------------------------------------------------
__device__ __nv_bfloat16 g_Wt_hi[17 * H_DIM * H_DIM];   // [r][o][i]  (N,K) K-major
__device__ __nv_bfloat16 g_Wt_lo[17 * H_DIM * H_DIM];
__device__ __nv_bfloat16 g_A_hi[(size_t)N_ENT * H_DIM];
__device__ __nv_bfloat16 g_A_lo[(size_t)N_ENT * H_DIM];
__device__ float         g_HR[(size_t)N_REL * N_ENT * H_DIM];
__device__ float         g_H1[(size_t)N_ENT * H_DIM];

// ---------------------------------------------------------------------------
// helpers
// ---------------------------------------------------------------------------
__device__ __forceinline__ uint32_t smem_u32(const void* p) {
    uint32_t a;
    asm("{ .reg .u64 t; cvta.to.shared.u64 t, %1; cvt.u32.u64 %0, t; }"
        : "=r"(a) : "l"(p));
    return a;
}

#define LDMX4(r0, r1, r2, r3, addr)                                           \
    asm volatile("ldmatrix.sync.aligned.m8n8.x4.shared.b16 {%0,%1,%2,%3}, [%4];" \
                 : "=r"(r0), "=r"(r1), "=r"(r2), "=r"(r3) : "r"(addr))

#define MMA_BF16(C, A, B)                                                     \
    asm volatile(                                                             \
        "mma.sync.aligned.m16n8k16.row.col.f32.bf16.bf16.f32 "                \
        "{%0,%1,%2,%3}, {%4,%5,%6,%7}, {%8,%9}, {%0,%1,%2,%3};"               \
        : "+f"((C)[0]), "+f"((C)[1]), "+f"((C)[2]), "+f"((C)[3])              \
        : "r"((A)[0]), "r"((A)[1]), "r"((A)[2]), "r"((A)[3]),                 \
          "r"((B)[0]), "r"((B)[1]))

// ---------------------------------------------------------------------------
// 1) Combine bases -> transposed bf16 hi/lo weights.
//    Wt[r][o][i] = sum_b w_comp[r,b]*basis[b,i,o];  r==16 -> loop_w
// ---------------------------------------------------------------------------
__global__ void combine_bases_kernel(const float* __restrict__ basis,
                                     const float* __restrict__ w_comp,
                                     const float* __restrict__ loop_w,
                                     __nv_bfloat16* __restrict__ Wt_hi,
                                     __nv_bfloat16* __restrict__ Wt_lo)
{
    int idx = blockIdx.x * blockDim.x + threadIdx.x;
    const int total = 17 * H_DIM * H_DIM;
    if (idx >= total) return;
    int r  = idx >> 14;
    int io = idx & 16383;          // i*128 + o
    float s;
    if (r < N_REL) {
        s = 0.f;
#pragma unroll
        for (int b = 0; b < N_BASES; b++)
            s += w_comp[r * N_BASES + b] * basis[b * (H_DIM * H_DIM) + io];
    } else {
        s = loop_w[io];
    }
    int i = io >> 7, o = io & 127;
    size_t oidx = (size_t)r * 16384 + o * 128 + i;   // [r][o][i]
    __nv_bfloat16 hi = __float2bfloat16(s);
    __nv_bfloat16 lo = __float2bfloat16(s - __bfloat162float(hi));
    Wt_hi[oidx] = hi;
    Wt_lo[oidx] = lo;
}

// ---------------------------------------------------------------------------
// 2) Split input activations fp32 -> bf16 hi/lo (optional fused ReLU).
// ---------------------------------------------------------------------------
__global__ void split_kernel(const float* __restrict__ x,
                             __nv_bfloat16* __restrict__ hi,
                             __nv_bfloat16* __restrict__ lo,
                             int n4, int relu)
{
    int i = blockIdx.x * blockDim.x + threadIdx.x;
    if (i >= n4) return;
    float4 v = ((const float4*)x)[i];
    if (relu) {
        v.x = fmaxf(v.x, 0.f); v.y = fmaxf(v.y, 0.f);
        v.z = fmaxf(v.z, 0.f); v.w = fmaxf(v.w, 0.f);
    }
    float e[4] = {v.x, v.y, v.z, v.w};
    __nv_bfloat16 h[4], l[4];
#pragma unroll
    for (int j = 0; j < 4; j++) {
        h[j] = __float2bfloat16(e[j]);
        l[j] = __float2bfloat16(e[j] - __bfloat162float(h[j]));
    }
    ((__nv_bfloat162*)hi)[2 * i]     = __nv_bfloat162(h[0], h[1]);
    ((__nv_bfloat162*)hi)[2 * i + 1] = __nv_bfloat162(h[2], h[3]);
    ((__nv_bfloat162*)lo)[2 * i]     = __nv_bfloat162(l[0], l[1]);
    ((__nv_bfloat162*)lo)[2 * i + 1] = __nv_bfloat162(l[2], l[3]);
}

// ---------------------------------------------------------------------------
// 3) bf16 mma.sync GEMM with A-tile reuse across all 17 relations.
//    Grid: (2 n-halves, ceil(M/128)). CTA: 256 thr = 8 warps (4M x 2N),
//    warp tile 32x32, 3-term bf16 split (Ah*Wh + Ah*Wl + Al*Wh).
//    A tile [128 x 128] hi+lo resident in smem for all 17 r's.
//    r < 16 -> HR[r];  r == 16 -> OUT (+bias)  [initializes OUT]
// ---------------------------------------------------------------------------
#define PITCH   272                    // 256B row + 16B pad (conflict-free ldmatrix)
#define SM_A_HI 0
#define SM_A_LO 34816                  // 128*272
#define SM_W_HI 69632
#define SM_W_LO 87040                  // + 64*272
#define GEMM_SMEM 104448               // 87040 + 17408

__global__ __launch_bounds__(256, 2)
void gemm_bf16_kernel(const __nv_bfloat16* __restrict__ Ahi,
                      const __nv_bfloat16* __restrict__ Alo,
                      const __nv_bfloat16* __restrict__ Wthi,
                      const __nv_bfloat16* __restrict__ Wtlo,
                      const float* __restrict__ bias,
                      float* __restrict__ HR,
                      float* __restrict__ OUT,
                      int M)
{
    extern __shared__ char smem[];
    const uint32_t sb = smem_u32(smem);
    const int tid   = threadIdx.x;
    const int wid   = tid >> 5;
    const int lane  = tid & 31;
    const int wm    = wid >> 1;             // 0..3
    const int wn    = wid & 1;              // 0..1
    const int nhalf = blockIdx.x;           // 0..1
    const int m0    = blockIdx.y * 128;

    // ---- load A tile (hi, lo): 128 rows x 128 bf16 each ----
#pragma unroll
    for (int t = 0; t < 2; t++) {
        const __nv_bfloat16* src = t ? Alo : Ahi;
        char* dstb = smem + (t ? SM_A_LO : SM_A_HI);
#pragma unroll
        for (int i = 0; i < 8; i++) {
            int idx = tid + i * 256;        // 0..2047
            int row = idx >> 4;
            int c   = idx & 15;
            uint4 v = make_uint4(0u, 0u, 0u, 0u);
            if (m0 + row < M)
                v = *(const uint4*)(src + (size_t)(m0 + row) * H_DIM + c * 8);
            *(uint4*)(dstb + row * PITCH + c * 16) = v;
        }
    }

    // ldmatrix per-lane address components (fixed across ksteps)
    const int q   = lane >> 3;               // 0..3
    const int r8  = lane & 7;
    const int arow_base = wm * 32 + r8 + (q & 1) * 8;     // + mt*16
    const int acol_add  = (q >> 1) * 8;                   // + k0
    const int brow_base = wn * 32 + (q >> 1) * 8 + r8;    // + p*16
    const int bcol_add  = (q & 1) * 8;                    // + k0

    for (int r = 0; r < 17; r++) {
        // ---- load W_r tile: 64 rows x 128 bf16, hi+lo ----
#pragma unroll
        for (int t = 0; t < 2; t++) {
            const __nv_bfloat16* src =
                (t ? Wtlo : Wthi) + (size_t)r * 16384 + (size_t)nhalf * 64 * H_DIM;
            char* dstb = smem + (t ? SM_W_LO : SM_W_HI);
#pragma unroll
            for (int i = 0; i < 4; i++) {
                int idx = tid + i * 256;    // 0..1023
                int row = idx >> 4;
                int c   = idx & 15;
                uint4 v = *(const uint4*)(src + (size_t)row * H_DIM + c * 8);
                *(uint4*)(dstb + row * PITCH + c * 16) = v;
            }
        }
        __syncthreads();

        float acc[2][4][4];
#pragma unroll
        for (int mt = 0; mt < 2; mt++)
#pragma unroll
            for (int nt = 0; nt < 4; nt++)
#pragma unroll
                for (int c = 0; c < 4; c++) acc[mt][nt][c] = 0.f;

#pragma unroll
        for (int ks = 0; ks < 8; ks++) {
            const int k0 = ks * 16;
            uint32_t ah[2][4], al[2][4], bh[4][2], bl[4][2];
#pragma unroll
            for (int mt = 0; mt < 2; mt++) {
                uint32_t off = (uint32_t)((arow_base + mt * 16) * PITCH
                                          + (k0 + acol_add) * 2);
                LDMX4(ah[mt][0], ah[mt][1], ah[mt][2], ah[mt][3], sb + SM_A_HI + off);
                LDMX4(al[mt][0], al[mt][1], al[mt][2], al[mt][3], sb + SM_A_LO + off);
            }
#pragma unroll
            for (int p = 0; p < 2; p++) {
                uint32_t off = (uint32_t)((brow_base + p * 16) * PITCH
                                          + (k0 + bcol_add) * 2);
                LDMX4(bh[2 * p][0], bh[2 * p][1], bh[2 * p + 1][0], bh[2 * p + 1][1],
                      sb + SM_W_HI + off);
                LDMX4(bl[2 * p][0], bl[2 * p][1], bl[2 * p + 1][0], bl[2 * p + 1][1],
                      sb + SM_W_LO + off);
            }
#pragma unroll
            for (int mt = 0; mt < 2; mt++)
#pragma unroll
                for (int nt = 0; nt < 4; nt++) {
                    MMA_BF16(acc[mt][nt], ah[mt], bh[nt]);
                    MMA_BF16(acc[mt][nt], ah[mt], bl[nt]);
                    MMA_BF16(acc[mt][nt], al[mt], bh[nt]);
                }
        }
        __syncthreads();   // all warps done reading W before next r overwrites it

        // ---- epilogue (registers -> global) ----
        float* base = (r < N_REL) ? (HR + (size_t)r * N_ENT * H_DIM) : OUT;
        const int gr0 = m0 + wm * 32 + (lane >> 2);
#pragma unroll
        for (int mt = 0; mt < 2; mt++) {
            int row = gr0 + mt * 16;
#pragma unroll
            for (int nt = 0; nt < 4; nt++) {
                int col = nhalf * 64 + wn * 32 + nt * 8 + (lane & 3) * 2;
                float b0 = 0.f, b1 = 0.f;
                if (r == N_REL) {
                    float2 bv = *(const float2*)(bias + col);
                    b0 = bv.x; b1 = bv.y;
                }
                if (row < M)
                    *(float2*)(base + (size_t)row * H_DIM + col) =
                        make_float2(acc[mt][nt][0] + b0, acc[mt][nt][1] + b1);
                if (row + 8 < M)
                    *(float2*)(base + (size_t)(row + 8) * H_DIM + col) =
                        make_float2(acc[mt][nt][2] + b0, acc[mt][nt][3] + b1);
            }
        }
    }
}

// ---------------------------------------------------------------------------
// 4) Edge scatter: out[dst] += HR[rel][src]. One warp per edge,
//    float4 gather + red.global.add.v4.f32.
// ---------------------------------------------------------------------------
__global__ void scatter_kernel(const float* __restrict__ HR,
                               const int* __restrict__ src,
                               const int* __restrict__ dst,
                               const int* __restrict__ rel,
                               float* __restrict__ out,
                               int E)
{
    int gtid = blockIdx.x * blockDim.x + threadIdx.x;
    int e    = gtid >> 5;
    int lane = gtid & 31;
    if (e >= E) return;
    int s = src[e];
    int d = dst[e];
    int r = rel[e];
    const float4 v = *(const float4*)(HR + ((size_t)r * N_ENT + s) * H_DIM + lane * 4);
    float* o = out + (size_t)d * H_DIM + lane * 4;
    asm volatile("red.global.add.v4.f32 [%0], {%1,%2,%3,%4};"
                 :: "l"(o), "f"(v.x), "f"(v.y), "f"(v.z), "f"(v.w)
                 : "memory");
}

// ---------------------------------------------------------------------------
// 5) Final ReLU.
// ---------------------------------------------------------------------------
__global__ void relu_kernel(float* __restrict__ x, int n4)
{
    int i = blockIdx.x * blockDim.x + threadIdx.x;
    if (i >= n4) return;
    float4 v = ((float4*)x)[i];
    v.x = fmaxf(v.x, 0.f); v.y = fmaxf(v.y, 0.f);
    v.z = fmaxf(v.z, 0.f); v.w = fmaxf(v.w, 0.f);
    ((float4*)x)[i] = v;
}

// ---------------------------------------------------------------------------
// Launch
// ---------------------------------------------------------------------------
extern "C" void kernel_launch(void* const* d_in, const int* in_sizes, int n_in,
                              void* d_out, int out_size)
{
    const float* entity_emb = (const float*)d_in[0];
    const float* basis1     = (const float*)d_in[1];
    const float* w_comp1    = (const float*)d_in[2];
    const float* loop_w1    = (const float*)d_in[3];
    const float* bias1      = (const float*)d_in[4];
    const float* basis2     = (const float*)d_in[5];
    const float* w_comp2    = (const float*)d_in[6];
    const float* loop_w2    = (const float*)d_in[7];
    const float* bias2      = (const float*)d_in[8];
    const int*   src        = (const int*)d_in[9];
    const int*   dst        = (const int*)d_in[10];
    const int*   rel        = (const int*)d_in[11];
    float*       out        = (float*)d_out;

    const int E = in_sizes[9];

    __nv_bfloat16 *dWth, *dWtl, *dAh, *dAl;
    float *dHR, *dH1;
    cudaGetSymbolAddress((void**)&dWth, g_Wt_hi);
    cudaGetSymbolAddress((void**)&dWtl, g_Wt_lo);
    cudaGetSymbolAddress((void**)&dAh,  g_A_hi);
    cudaGetSymbolAddress((void**)&dAl,  g_A_lo);
    cudaGetSymbolAddress((void**)&dHR,  g_HR);
    cudaGetSymbolAddress((void**)&dH1,  g_H1);

    cudaFuncSetAttribute(gemm_bf16_kernel,
                         cudaFuncAttributeMaxDynamicSharedMemorySize, GEMM_SMEM);

    const int cb_total  = 17 * H_DIM * H_DIM;
    const int cb_blocks = (cb_total + 255) / 256;
    const int n4        = N_ENT * H_DIM / 4;
    const int sp_blocks = (n4 + 255) / 256;
    dim3 gemm_grid(2, (N_ENT + 127) / 128);
    const int scat_blocks = (E * 32 + 255) / 256;

    // ---------------- Layer 1 ----------------
    combine_bases_kernel<<<cb_blocks, 256>>>(basis1, w_comp1, loop_w1, dWth, dWtl);
    split_kernel<<<sp_blocks, 256>>>(entity_emb, dAh, dAl, n4, 0);
    gemm_bf16_kernel<<<gemm_grid, 256, GEMM_SMEM>>>(dAh, dAl, dWth, dWtl, bias1,
                                                    dHR, dH1, N_ENT);
    scatter_kernel<<<scat_blocks, 256>>>(dHR, src, dst, rel, dH1, E);

    // ---------------- Layer 2 ----------------
    combine_bases_kernel<<<cb_blocks, 256>>>(basis2, w_comp2, loop_w2, dWth, dWtl);
    split_kernel<<<sp_blocks, 256>>>(dH1, dAh, dAl, n4, 1);   // fused ReLU
    gemm_bf16_kernel<<<gemm_grid, 256, GEMM_SMEM>>>(dAh, dAl, dWth, dWtl, bias2,
                                                    dHR, out, N_ENT);
    scatter_kernel<<<scat_blocks, 256>>>(dHR, src, dst, rel, out, E);
    relu_kernel<<<sp_blocks, 256>>>(out, n4);
}